// round 12
// baseline (speedup 1.0000x reference)
#include <cuda_runtime.h>
#include <cuda_fp16.h>
#include <math.h>
#include <stdint.h>

#define Bv  4
#define Tv  2048
#define Cv  2048
#define Hv  16
#define HDv 128
#define BHv (Bv*Hv)

// ---------------- scratch (device globals; no allocation allowed) ----------------
__device__ float  g_q [(size_t)BHv * Tv * HDv];    // fp32 Q (pre-rope)
__device__ float  g_k [(size_t)BHv * Tv * HDv];
__device__ __half g_qh[(size_t)BHv * Tv * HDv];    // fp16 post-rope (scale folded in Q)
__device__ __half g_kh[(size_t)BHv * Tv * HDv];
__device__ __half g_vh[(size_t)BHv * Tv * HDv];
__device__ __half g_yh[(size_t)Bv * Tv * Cv];      // attention out (fp16)
__device__ __half g_xh[(size_t)Bv * Tv * Cv];      // x in fp16
__device__ __half g_wh[(size_t)4 * Cv * Cv];       // wq,wk,wv,wo in fp16 (contiguous)

__device__ __forceinline__ unsigned h2pack(float a, float b) {
    __half2 h = __floats2half2_rn(a, b);
    return *(unsigned*)&h;
}
__device__ __forceinline__ uint32_t smem_u32(const void* p) {
    uint32_t a;
    asm("{ .reg .u64 t; cvta.to.shared.u64 t, %1; cvt.u32.u64 %0, t; }" : "=r"(a) : "l"(p));
    return a;
}
__device__ __forceinline__ void mma_h(float* c, unsigned a0, unsigned a1, unsigned a2,
                                      unsigned a3, unsigned b0, unsigned b1) {
    asm volatile(
        "mma.sync.aligned.m16n8k16.row.col.f32.f16.f16.f32 "
        "{%0,%1,%2,%3}, {%4,%5,%6,%7}, {%8,%9}, {%0,%1,%2,%3};\n"
        : "+f"(c[0]), "+f"(c[1]), "+f"(c[2]), "+f"(c[3])
        : "r"(a0), "r"(a1), "r"(a2), "r"(a3), "r"(b0), "r"(b1));
}
__device__ __forceinline__ void cp16(uint32_t sdst, const void* gsrc) {
    asm volatile("cp.async.cg.shared.global [%0], [%1], 16;" :: "r"(sdst), "l"(gsrc));
}
#define CP_COMMIT() asm volatile("cp.async.commit_group;" ::: "memory")
#define CP_WAIT2()  asm volatile("cp.async.wait_group 2;" ::: "memory")
#define CP_WAIT1()  asm volatile("cp.async.wait_group 1;" ::: "memory")
#define CP_WAIT0()  asm volatile("cp.async.wait_group 0;" ::: "memory")

__device__ __forceinline__ void ldm4(uint4& v, uint32_t addr) {
    asm volatile("ldmatrix.sync.aligned.m8n8.x4.shared.b16 {%0,%1,%2,%3}, [%4];"
                 : "=r"(v.x), "=r"(v.y), "=r"(v.z), "=r"(v.w) : "r"(addr));
}
__device__ __forceinline__ void ldm4t(uint4& v, uint32_t addr) {
    asm volatile("ldmatrix.sync.aligned.m8n8.x4.trans.shared.b16 {%0,%1,%2,%3}, [%4];"
                 : "=r"(v.x), "=r"(v.y), "=r"(v.z), "=r"(v.w) : "r"(addr));
}

// 64B-row tiles (BK=32): chunk index
__device__ __forceinline__ int sw16(int r, int c) {
    return ((r >> 1) << 3) + ((((r & 1) << 2) + c) ^ ((r >> 1) & 7));
}
// 256B-row tiles (attention): byte addr
__device__ __forceinline__ uint32_t sw256(int r, int c) {
    return (uint32_t)(r * 256 + ((c ^ (r & 7)) << 4));
}

// ---------------- fused pre-convert fp32 -> fp16 (x + 4 weights) ----------------
#define NXe ((size_t)Bv * Tv * Cv)
#define NWe ((size_t)Cv * Cv)
__global__ void cvt_all(const float* __restrict__ x,  const float* __restrict__ wq,
                        const float* __restrict__ wk, const float* __restrict__ wv,
                        const float* __restrict__ wo)
{
    size_t f = ((size_t)blockIdx.x * blockDim.x + threadIdx.x) * 4;
    const float* src;
    __half* dst;
    if (f < NXe) { src = x + f; dst = g_xh + f; }
    else {
        size_t f2 = f - NXe;
        int widx = (int)(f2 / NWe);
        size_t off = f2 - (size_t)widx * NWe;
        const float* ws[4] = { wq, wk, wv, wo };
        src = ws[widx] + off;
        dst = g_wh + f2;
    }
    float4 v = *(const float4*)src;
    *(uint2*)dst = make_uint2(h2pack(v.x, v.y), h2pack(v.z, v.w));
}

// ========== fp16 GEMM, 128x256 CTA tile, 64x64 warp tile, BK=32, 4-stage ==========
// out[r,o] = sum_c A[r,c] * W[o,c]
// dst_mode: 4 -> merged QKV scatter (o in [0,6144)), 3 -> Oext fp32 [r,o]
// smem per stage: A 128x32 fp16 = 8KB, B 256x32 fp16 = 16KB -> 24KB; 4 stages = 96KB
#define GEMM_STAGE_BYTES 24576
#define GEMM_SMEM_BYTES (4 * GEMM_STAGE_BYTES)

__global__ __launch_bounds__(256, 1) void h16gemm(const __half* __restrict__ A,
                                                  const __half* __restrict__ W,
                                                  float* __restrict__ Oext,
                                                  int dst_mode)
{
    extern __shared__ __align__(1024) char smraw[];
    uint32_t sbase = smem_u32(smraw);

    int tid = threadIdx.x;
    int lane = tid & 31;
    int wid = tid >> 5;
    int g = lane >> 2;
    int tg = lane & 3;
    int lrow = lane & 7;
    int sel = lane >> 3;
    int bm = blockIdx.y * 128;
    int bn = blockIdx.x * 256;
    int wm = (wid & 1) * 64;     // 2 m-warps
    int wn = (wid >> 1) * 64;    // 4 n-warps

    // staging: r0 = tid>>2 (0..63), c0 = tid&3
    int r0 = tid >> 2;
    int c0 = tid & 3;
    const __half* gA  = A + (size_t)(bm + r0) * Cv + c0 * 8;
    const __half* gA2 = gA + (size_t)64 * Cv;
    const __half* gB  = W + (size_t)(bn + r0) * Cv + c0 * 8;
    const __half* gB2 = gB + (size_t)64 * Cv;
    const __half* gB3 = gB + (size_t)128 * Cv;
    const __half* gB4 = gB + (size_t)192 * Cv;
    uint32_t aof0 = sw16(r0, c0) * 16;
    uint32_t aof1 = sw16(r0 + 64, c0) * 16;
    uint32_t bof0 = 8192 + sw16(r0, c0) * 16;
    uint32_t bof1 = 8192 + sw16(r0 + 64, c0) * 16;
    uint32_t bof2 = 8192 + sw16(r0 + 128, c0) * 16;
    uint32_t bof3 = 8192 + sw16(r0 + 192, c0) * 16;

    float c[4][8][4];
#pragma unroll
    for (int i = 0; i < 4; i++)
#pragma unroll
        for (int j = 0; j < 8; j++)
#pragma unroll
            for (int e = 0; e < 4; e++) c[i][j][e] = 0.0f;

    const int NIT = Cv / 32;   // 64

#define ISSUE(st) do {                                                  \
        uint32_t s_ = sbase + ((st) & 3) * GEMM_STAGE_BYTES;            \
        size_t k_ = (size_t)(st) * 32;                                  \
        cp16(s_ + aof0, gA  + k_);                                      \
        cp16(s_ + aof1, gA2 + k_);                                      \
        cp16(s_ + bof0, gB  + k_);                                      \
        cp16(s_ + bof1, gB2 + k_);                                      \
        cp16(s_ + bof2, gB3 + k_);                                      \
        cp16(s_ + bof3, gB4 + k_);                                      \
        CP_COMMIT();                                                    \
    } while (0)

    ISSUE(0);
    ISSUE(1);
    ISSUE(2);

    for (int it = 0; it < NIT; it++) {
        if (it < NIT - 2) CP_WAIT2();
        else if (it == NIT - 2) CP_WAIT1();
        else CP_WAIT0();
        __syncthreads();

        uint32_t ab = sbase + (it & 3) * GEMM_STAGE_BYTES;
        uint32_t bb = ab + 8192;
#pragma unroll
        for (int ks = 0; ks < 2; ks++) {
            uint4 a[4];
#pragma unroll
            for (int i = 0; i < 4; i++) {
                int row = wm + i * 16 + ((sel & 1) << 3) + lrow;
                int ch  = 2 * ks + (sel >> 1);
                ldm4(a[i], ab + sw16(row, ch) * 16);
            }
#pragma unroll
            for (int p = 0; p < 4; p++) {
                int row = wn + p * 16 + ((sel >> 1) << 3) + lrow;
                int ch  = 2 * ks + (sel & 1);
                uint4 bv;
                ldm4(bv, bb + sw16(row, ch) * 16);
#pragma unroll
                for (int i = 0; i < 4; i++) {
                    mma_h(c[i][2 * p],     a[i].x, a[i].y, a[i].z, a[i].w, bv.x, bv.y);
                    mma_h(c[i][2 * p + 1], a[i].x, a[i].y, a[i].z, a[i].w, bv.z, bv.w);
                }
            }
        }
        if (it + 3 < NIT) ISSUE(it + 3);
    }
#undef ISSUE

    if (dst_mode == 3) {
#pragma unroll
        for (int i = 0; i < 4; i++)
#pragma unroll
            for (int j = 0; j < 8; j++) {
                int r = bm + wm + i * 16 + g;
                int o = bn + wn + j * 8 + tg * 2;
                *(float2*)&Oext[(size_t)r * Cv + o] = make_float2(c[i][j][0], c[i][j][1]);
                *(float2*)&Oext[(size_t)(r + 8) * Cv + o] = make_float2(c[i][j][2], c[i][j][3]);
            }
    } else {
        // merged QKV scatter: o in [0, 6144)
#pragma unroll
        for (int i = 0; i < 4; i++)
#pragma unroll
            for (int j = 0; j < 8; j++) {
                int r = bm + wm + i * 16 + g;
                int o = bn + wn + j * 8 + tg * 2;
                int widx = o >> 11;          // 0=q, 1=k, 2=v
                int o2 = o & 2047;
                int b_ = r >> 11, t = r & 2047;
                int h = o2 >> 7, d = o2 & 127;
                size_t off = (((size_t)(b_ * Hv + h) * Tv) + t) * HDv + d;
                if (widx == 2) {
                    *(unsigned*)&g_vh[off] = h2pack(c[i][j][0], c[i][j][1]);
                    *(unsigned*)&g_vh[off + (size_t)8 * HDv] = h2pack(c[i][j][2], c[i][j][3]);
                } else {
                    float* outp = (widx == 0) ? g_q : g_k;
                    *(float2*)&outp[off] = make_float2(c[i][j][0], c[i][j][1]);
                    *(float2*)&outp[off + (size_t)8 * HDv] = make_float2(c[i][j][2], c[i][j][3]);
                }
            }
    }
}

// ---------------- RoPE: fp32 -> fp16 (scale folded into Q) ----------------
__global__ void rope_kernel()
{
    int idx = blockIdx.x * blockDim.x + threadIdx.x;
    int i  = idx & 63;
    int t  = (idx >> 6) & 2047;
    int bh = idx >> 17;
    if (bh >= BHv) return;

    float inv = (float)pow(10000.0, -(double)i / 64.0);
    float f = (float)t * inv;
    float c = cosf(f), s = sinf(f);
    const float scale = 0.08838834764831845f;   // 1/sqrt(128)

    size_t base = ((size_t)bh * Tv + t) * HDv;
    float q1 = g_q[base + i], q2 = g_q[base + i + 64];
    g_qh[base + i]      = __float2half((q1 * c - q2 * s) * scale);
    g_qh[base + i + 64] = __float2half((q2 * c + q1 * s) * scale);
    float k1 = g_k[base + i], k2 = g_k[base + i + 64];
    g_kh[base + i]      = __float2half(k1 * c - k2 * s);
    g_kh[base + i + 64] = __float2half(k2 * c + k1 * s);
}

// ================= fp16 flash attention (R11-proven): Q in regs, 2-stage KV ========
#define ATT_SMEM_BYTES (16384 + 2 * 32768)

__global__ __launch_bounds__(128, 2) void attn_kernel()
{
    extern __shared__ __align__(1024) char smraw[];
    uint32_t sbase = smem_u32(smraw);

    int bh = blockIdx.y;
    int qb = gridDim.x - 1 - blockIdx.x;   // long CTAs first
    int q0 = qb * 64;
    int tid = threadIdx.x;
    int lane = tid & 31;
    int w = tid >> 5;
    int g = lane >> 2;
    int tg = lane & 3;
    int lrow = lane & 7;
    int sel = lane >> 3;
    size_t base = (size_t)bh * Tv * HDv;

#define ISSUE_KV(kt) do {                                                        \
        uint32_t kb_ = sbase + 16384 + ((kt) & 1) * 32768;                       \
        int k0_ = (kt) * 64;                                                     \
        for (int i = tid; i < 1024; i += 128) {                                  \
            int r_ = i >> 4, c_ = i & 15;                                        \
            cp16(kb_ + sw256(r_, c_),         &g_kh[base + (size_t)(k0_ + r_) * HDv + c_ * 8]); \
            cp16(kb_ + 16384 + sw256(r_, c_), &g_vh[base + (size_t)(k0_ + r_) * HDv + c_ * 8]); \
        }                                                                        \
        CP_COMMIT();                                                             \
    } while (0)

    for (int i = tid; i < 1024; i += 128) {
        int r = i >> 4, c = i & 15;
        cp16(sbase + sw256(r, c), &g_qh[base + (size_t)(q0 + r) * HDv + c * 8]);
    }
    {
        uint32_t kb = sbase + 16384;
        for (int i = tid; i < 1024; i += 128) {
            int r = i >> 4, c = i & 15;
            cp16(kb + sw256(r, c),         &g_kh[base + (size_t)r * HDv + c * 8]);
            cp16(kb + 16384 + sw256(r, c), &g_vh[base + (size_t)r * HDv + c * 8]);
        }
        CP_COMMIT();
    }
    if (qb >= 1) { ISSUE_KV(1); CP_WAIT1(); } else { CP_WAIT0(); }
    __syncthreads();

    uint4 aq[8];
#pragma unroll
    for (int ks = 0; ks < 8; ks++) {
        int row = w * 16 + ((sel & 1) << 3) + lrow;
        int ch  = ks * 2 + (sel >> 1);
        ldm4(aq[ks], sbase + sw256(row, ch));
    }

    float o[16][4];
#pragma unroll
    for (int nt = 0; nt < 16; nt++)
#pragma unroll
        for (int e = 0; e < 4; e++) o[nt][e] = 0.0f;
    float mrow0 = -1e30f, mrow1 = -1e30f;
    float lrow0 = 0.0f,   lrow1 = 0.0f;

    for (int kt = 0; kt <= qb; kt++) {
        if (kt < qb) CP_WAIT1(); else CP_WAIT0();
        __syncthreads();

        uint32_t kb = sbase + 16384 + (kt & 1) * 32768;
        uint32_t vb = kb + 16384;
        int k0 = kt * 64;

        float s[8][4];
#pragma unroll
        for (int nt = 0; nt < 8; nt++)
#pragma unroll
            for (int e = 0; e < 4; e++) s[nt][e] = 0.0f;
#pragma unroll
        for (int ks = 0; ks < 8; ks++) {
#pragma unroll
            for (int nt = 0; nt < 4; nt++) {
                int row = nt * 16 + ((sel >> 1) << 3) + lrow;
                int ch  = ks * 2 + (sel & 1);
                uint4 bk;
                ldm4(bk, kb + sw256(row, ch));
                mma_h(s[2 * nt],     aq[ks].x, aq[ks].y, aq[ks].z, aq[ks].w, bk.x, bk.y);
                mma_h(s[2 * nt + 1], aq[ks].x, aq[ks].y, aq[ks].z, aq[ks].w, bk.z, bk.w);
            }
        }

        if (kt == qb) {
            int row0 = q0 + w * 16 + g;
#pragma unroll
            for (int nt = 0; nt < 8; nt++)
#pragma unroll
                for (int e2 = 0; e2 < 4; e2++) {
                    int col = k0 + nt * 8 + tg * 2 + (e2 & 1);
                    int rr = row0 + (e2 >> 1) * 8;
                    if (col > rr) s[nt][e2] = -1e30f;
                }
        }

        float mx0 = -1e30f, mx1 = -1e30f;
#pragma unroll
        for (int nt = 0; nt < 8; nt++) {
            mx0 = fmaxf(mx0, fmaxf(s[nt][0], s[nt][1]));
            mx1 = fmaxf(mx1, fmaxf(s[nt][2], s[nt][3]));
        }
        mx0 = fmaxf(mx0, __shfl_xor_sync(0xffffffffu, mx0, 1));
        mx0 = fmaxf(mx0, __shfl_xor_sync(0xffffffffu, mx0, 2));
        mx1 = fmaxf(mx1, __shfl_xor_sync(0xffffffffu, mx1, 1));
        mx1 = fmaxf(mx1, __shfl_xor_sync(0xffffffffu, mx1, 2));

        float mn0 = fmaxf(mrow0, mx0);
        float mn1 = fmaxf(mrow1, mx1);
        float al0 = __expf(mrow0 - mn0);
        float al1 = __expf(mrow1 - mn1);
        mrow0 = mn0; mrow1 = mn1;

        float rs0 = 0.0f, rs1 = 0.0f;
#pragma unroll
        for (int nt = 0; nt < 8; nt++) {
            float p0 = __expf(s[nt][0] - mn0);
            float p1 = __expf(s[nt][1] - mn0);
            float p2 = __expf(s[nt][2] - mn1);
            float p3 = __expf(s[nt][3] - mn1);
            rs0 += p0 + p1; rs1 += p2 + p3;
            s[nt][0] = p0; s[nt][1] = p1; s[nt][2] = p2; s[nt][3] = p3;
        }
        rs0 += __shfl_xor_sync(0xffffffffu, rs0, 1);
        rs0 += __shfl_xor_sync(0xffffffffu, rs0, 2);
        rs1 += __shfl_xor_sync(0xffffffffu, rs1, 1);
        rs1 += __shfl_xor_sync(0xffffffffu, rs1, 2);
        lrow0 = lrow0 * al0 + rs0;
        lrow1 = lrow1 * al1 + rs1;

#pragma unroll
        for (int nt = 0; nt < 16; nt++) {
            o[nt][0] *= al0; o[nt][1] *= al0;
            o[nt][2] *= al1; o[nt][3] *= al1;
        }

#pragma unroll
        for (int ks2 = 0; ks2 < 4; ks2++) {
            unsigned a0 = h2pack(s[2 * ks2][0],     s[2 * ks2][1]);
            unsigned a1 = h2pack(s[2 * ks2][2],     s[2 * ks2][3]);
            unsigned a2 = h2pack(s[2 * ks2 + 1][0], s[2 * ks2 + 1][1]);
            unsigned a3 = h2pack(s[2 * ks2 + 1][2], s[2 * ks2 + 1][3]);
#pragma unroll
            for (int nt = 0; nt < 8; nt++) {
                int row = ks2 * 16 + ((sel & 1) << 3) + lrow;
                int ch  = nt * 2 + (sel >> 1);
                uint4 bv;
                ldm4t(bv, vb + sw256(row, ch));
                mma_h(o[2 * nt],     a0, a1, a2, a3, bv.x, bv.y);
                mma_h(o[2 * nt + 1], a0, a1, a2, a3, bv.z, bv.w);
            }
        }

        if (kt + 2 <= qb) {
            __syncthreads();
            ISSUE_KV(kt + 2);
        }
    }
#undef ISSUE_KV

    int b = bh >> 4;
    int hh = bh & 15;
#pragma unroll
    for (int h = 0; h < 2; h++) {
        float invl = 1.0f / (h ? lrow1 : lrow0);
        int t = q0 + w * 16 + g + h * 8;
        __half* op = g_yh + ((size_t)(b * Tv + t)) * Cv + hh * HDv;
#pragma unroll
        for (int nt = 0; nt < 16; nt++) {
            int d = nt * 8 + tg * 2;
            *(unsigned*)&op[d] = h2pack(o[nt][2 * h] * invl, o[nt][2 * h + 1] * invl);
        }
    }
}

// ---------------- launch ----------------
extern "C" void kernel_launch(void* const* d_in, const int* in_sizes, int n_in,
                              void* d_out, int out_size)
{
    const float* x  = (const float*)d_in[0];
    const float* wq = (const float*)d_in[2];
    const float* wk = (const float*)d_in[3];
    const float* wv = (const float*)d_in[4];
    const float* wo = (const float*)d_in[5];
    float* out = (float*)d_out;

    __half* whp = nullptr;
    __half* xhp = nullptr;
    __half* yhp = nullptr;
    cudaGetSymbolAddress((void**)&whp, g_wh);
    cudaGetSymbolAddress((void**)&xhp, g_xh);
    cudaGetSymbolAddress((void**)&yhp, g_yh);
    cudaFuncSetAttribute(h16gemm, cudaFuncAttributeMaxDynamicSharedMemorySize,
                         GEMM_SMEM_BYTES);
    cudaFuncSetAttribute(attn_kernel, cudaFuncAttributeMaxDynamicSharedMemorySize,
                         ATT_SMEM_BYTES);

    // fused conversions
    cvt_all<<<(unsigned)((NXe + 4 * NWe) / 1024), 256>>>(x, wq, wk, wv, wo);

    // merged QKV projection: N = 6144, CTA tile 128x256
    h16gemm<<<dim3(24, 64), 256, GEMM_SMEM_BYTES>>>(xhp, whp, nullptr, 4);

    rope_kernel<<<(BHv * Tv * 64) / 256, 256>>>();

    attn_kernel<<<dim3(Tv / 64, BHv), 128, ATT_SMEM_BYTES>>>();

    // output projection: N = 2048
    h16gemm<<<dim3(8, 64), 256, GEMM_SMEM_BYTES>>>(yhp, whp + 3 * NWe, out, 3);
}

// round 13
// speedup vs baseline: 1.0991x; 1.0991x over previous
#include <cuda_runtime.h>
#include <cuda_fp16.h>
#include <math.h>
#include <stdint.h>

#define Bv  4
#define Tv  2048
#define Cv  2048
#define Hv  16
#define HDv 128
#define BHv (Bv*Hv)

// ---------------- scratch (device globals; no allocation allowed) ----------------
__device__ float  g_q [(size_t)BHv * Tv * HDv];    // fp32 Q (pre-rope)
__device__ float  g_k [(size_t)BHv * Tv * HDv];
__device__ __half g_qh[(size_t)BHv * Tv * HDv];    // fp16 post-rope (scale folded in Q)
__device__ __half g_kh[(size_t)BHv * Tv * HDv];
__device__ __half g_vh[(size_t)BHv * Tv * HDv];
__device__ __half g_yh[(size_t)Bv * Tv * Cv];      // attention out (fp16)
__device__ __half g_xh[(size_t)Bv * Tv * Cv];      // x in fp16
__device__ __half g_wh[(size_t)4 * Cv * Cv];       // wq,wk,wv,wo in fp16 (contiguous)

__device__ __forceinline__ unsigned h2pack(float a, float b) {
    __half2 h = __floats2half2_rn(a, b);
    return *(unsigned*)&h;
}
__device__ __forceinline__ uint32_t smem_u32(const void* p) {
    uint32_t a;
    asm("{ .reg .u64 t; cvta.to.shared.u64 t, %1; cvt.u32.u64 %0, t; }" : "=r"(a) : "l"(p));
    return a;
}
__device__ __forceinline__ void mma_h(float* c, unsigned a0, unsigned a1, unsigned a2,
                                      unsigned a3, unsigned b0, unsigned b1) {
    asm volatile(
        "mma.sync.aligned.m16n8k16.row.col.f32.f16.f16.f32 "
        "{%0,%1,%2,%3}, {%4,%5,%6,%7}, {%8,%9}, {%0,%1,%2,%3};\n"
        : "+f"(c[0]), "+f"(c[1]), "+f"(c[2]), "+f"(c[3])
        : "r"(a0), "r"(a1), "r"(a2), "r"(a3), "r"(b0), "r"(b1));
}
__device__ __forceinline__ void cp16(uint32_t sdst, const void* gsrc) {
    asm volatile("cp.async.cg.shared.global [%0], [%1], 16;" :: "r"(sdst), "l"(gsrc));
}
#define CP_COMMIT() asm volatile("cp.async.commit_group;" ::: "memory")
#define CP_WAIT1()  asm volatile("cp.async.wait_group 1;" ::: "memory")
#define CP_WAIT0()  asm volatile("cp.async.wait_group 0;" ::: "memory")

__device__ __forceinline__ void ldm4(uint4& v, uint32_t addr) {
    asm volatile("ldmatrix.sync.aligned.m8n8.x4.shared.b16 {%0,%1,%2,%3}, [%4];"
                 : "=r"(v.x), "=r"(v.y), "=r"(v.z), "=r"(v.w) : "r"(addr));
}
__device__ __forceinline__ void ldm4t(uint4& v, uint32_t addr) {
    asm volatile("ldmatrix.sync.aligned.m8n8.x4.trans.shared.b16 {%0,%1,%2,%3}, [%4];"
                 : "=r"(v.x), "=r"(v.y), "=r"(v.z), "=r"(v.w) : "r"(addr));
}

// 64B-row tiles (32-col chunk): chunk index
__device__ __forceinline__ int sw16(int r, int c) {
    return ((r >> 1) << 3) + ((((r & 1) << 2) + c) ^ ((r >> 1) & 7));
}
// 256B-row tiles (attention): byte addr
__device__ __forceinline__ uint32_t sw256(int r, int c) {
    return (uint32_t)(r * 256 + ((c ^ (r & 7)) << 4));
}

// ---------------- fused pre-convert fp32 -> fp16 (x + 4 weights) ----------------
#define NXe ((size_t)Bv * Tv * Cv)
#define NWe ((size_t)Cv * Cv)
__global__ void cvt_all(const float* __restrict__ x,  const float* __restrict__ wq,
                        const float* __restrict__ wk, const float* __restrict__ wv,
                        const float* __restrict__ wo)
{
    size_t f = ((size_t)blockIdx.x * blockDim.x + threadIdx.x) * 4;
    const float* src;
    __half* dst;
    if (f < NXe) { src = x + f; dst = g_xh + f; }
    else {
        size_t f2 = f - NXe;
        int widx = (int)(f2 / NWe);
        size_t off = f2 - (size_t)widx * NWe;
        const float* ws[4] = { wq, wk, wv, wo };
        src = ws[widx] + off;
        dst = g_wh + f2;
    }
    float4 v = *(const float4*)src;
    *(uint2*)dst = make_uint2(h2pack(v.x, v.y), h2pack(v.z, v.w));
}

// ========== fp16 GEMM: 128x128 CTA, 32x64 warp tile, 3 stages of BK=64 ==========
// Stage (32KB): A chunk0 @0, A chunk1 @8192, B chunk0 @16384, B chunk1 @24576.
// One __syncthreads per 64-mma window; issue next stage at window end (R8 invariant).
// dst_mode: 4 -> merged QKV scatter (o in [0,6144)), 3 -> Oext fp32 [r,o]
#define GEMM_STAGE_BYTES 32768
#define GEMM_SMEM_BYTES (3 * GEMM_STAGE_BYTES)

__global__ __launch_bounds__(256, 2) void h16gemm(const __half* __restrict__ A,
                                                  const __half* __restrict__ W,
                                                  float* __restrict__ Oext,
                                                  int dst_mode)
{
    extern __shared__ __align__(1024) char smraw[];
    uint32_t sbase = smem_u32(smraw);

    int tid = threadIdx.x;
    int lane = tid & 31;
    int wid = tid >> 5;
    int g = lane >> 2;
    int tg = lane & 3;
    int lrow = lane & 7;
    int sel = lane >> 3;
    int bm = blockIdx.y * 128;
    int bn = blockIdx.x * 128;
    int wm = (wid & 3) * 32;
    int wn = (wid >> 2) * 64;

    int r0 = tid >> 2;          // 0..63
    int c0 = tid & 3;
    const __half* gA  = A + (size_t)(bm + r0) * Cv + c0 * 8;
    const __half* gA2 = gA + (size_t)64 * Cv;
    const __half* gB  = W + (size_t)(bn + r0) * Cv + c0 * 8;
    const __half* gB2 = gB + (size_t)64 * Cv;
    uint32_t of0 = sw16(r0, c0) * 16;
    uint32_t of1 = sw16(r0 + 64, c0) * 16;

    float c[2][8][4];
#pragma unroll
    for (int i = 0; i < 2; i++)
#pragma unroll
        for (int j = 0; j < 8; j++)
#pragma unroll
            for (int e = 0; e < 4; e++) c[i][j][e] = 0.0f;

    const int NWIN = Cv / 64;   // 32 windows

#define ISSUE(st) do {                                                  \
        uint32_t s_ = sbase + ((st) % 3) * GEMM_STAGE_BYTES;            \
        size_t k_ = (size_t)(st) * 64;                                  \
        cp16(s_ + of0,          gA  + k_);                              \
        cp16(s_ + of1,          gA2 + k_);                              \
        cp16(s_ + 8192  + of0,  gA  + k_ + 32);                         \
        cp16(s_ + 8192  + of1,  gA2 + k_ + 32);                         \
        cp16(s_ + 16384 + of0,  gB  + k_);                              \
        cp16(s_ + 16384 + of1,  gB2 + k_);                              \
        cp16(s_ + 24576 + of0,  gB  + k_ + 32);                         \
        cp16(s_ + 24576 + of1,  gB2 + k_ + 32);                         \
        CP_COMMIT();                                                    \
    } while (0)

    ISSUE(0);
    ISSUE(1);

    for (int w = 0; w < NWIN; w++) {
        if (w < NWIN - 1) CP_WAIT1(); else CP_WAIT0();
        __syncthreads();

        uint32_t stg = sbase + (w % 3) * GEMM_STAGE_BYTES;
#pragma unroll
        for (int kc = 0; kc < 2; kc++) {
            uint32_t ab = stg + kc * 8192;
            uint32_t bb = stg + 16384 + kc * 8192;
#pragma unroll
            for (int ks = 0; ks < 2; ks++) {
                uint4 a[2];
#pragma unroll
                for (int i = 0; i < 2; i++) {
                    int row = wm + i * 16 + ((sel & 1) << 3) + lrow;
                    int ch  = 2 * ks + (sel >> 1);
                    ldm4(a[i], ab + sw16(row, ch) * 16);
                }
#pragma unroll
                for (int p = 0; p < 4; p++) {
                    int row = wn + p * 16 + ((sel >> 1) << 3) + lrow;
                    int ch  = 2 * ks + (sel & 1);
                    uint4 bv;
                    ldm4(bv, bb + sw16(row, ch) * 16);
                    mma_h(c[0][2 * p],     a[0].x, a[0].y, a[0].z, a[0].w, bv.x, bv.y);
                    mma_h(c[0][2 * p + 1], a[0].x, a[0].y, a[0].z, a[0].w, bv.z, bv.w);
                    mma_h(c[1][2 * p],     a[1].x, a[1].y, a[1].z, a[1].w, bv.x, bv.y);
                    mma_h(c[1][2 * p + 1], a[1].x, a[1].y, a[1].z, a[1].w, bv.z, bv.w);
                }
            }
        }
        if (w + 2 < NWIN) ISSUE(w + 2);
    }
#undef ISSUE

    if (dst_mode == 3) {
#pragma unroll
        for (int i = 0; i < 2; i++)
#pragma unroll
            for (int j = 0; j < 8; j++) {
                int r = bm + wm + i * 16 + g;
                int o = bn + wn + j * 8 + tg * 2;
                *(float2*)&Oext[(size_t)r * Cv + o] = make_float2(c[i][j][0], c[i][j][1]);
                *(float2*)&Oext[(size_t)(r + 8) * Cv + o] = make_float2(c[i][j][2], c[i][j][3]);
            }
    } else {
        // merged QKV scatter: o in [0, 6144)
#pragma unroll
        for (int i = 0; i < 2; i++)
#pragma unroll
            for (int j = 0; j < 8; j++) {
                int r = bm + wm + i * 16 + g;
                int o = bn + wn + j * 8 + tg * 2;
                int widx = o >> 11;          // 0=q, 1=k, 2=v
                int o2 = o & 2047;
                int b_ = r >> 11, t = r & 2047;
                int h = o2 >> 7, d = o2 & 127;
                size_t off = (((size_t)(b_ * Hv + h) * Tv) + t) * HDv + d;
                if (widx == 2) {
                    *(unsigned*)&g_vh[off] = h2pack(c[i][j][0], c[i][j][1]);
                    *(unsigned*)&g_vh[off + (size_t)8 * HDv] = h2pack(c[i][j][2], c[i][j][3]);
                } else {
                    float* outp = (widx == 0) ? g_q : g_k;
                    *(float2*)&outp[off] = make_float2(c[i][j][0], c[i][j][1]);
                    *(float2*)&outp[off + (size_t)8 * HDv] = make_float2(c[i][j][2], c[i][j][3]);
                }
            }
    }
}

// ---------------- RoPE: fp32 -> fp16 (scale folded into Q) ----------------
__global__ void rope_kernel()
{
    int idx = blockIdx.x * blockDim.x + threadIdx.x;
    int i  = idx & 63;
    int t  = (idx >> 6) & 2047;
    int bh = idx >> 17;
    if (bh >= BHv) return;

    float inv = (float)pow(10000.0, -(double)i / 64.0);
    float f = (float)t * inv;
    float c = cosf(f), s = sinf(f);
    const float scale = 0.08838834764831845f;   // 1/sqrt(128)

    size_t base = ((size_t)bh * Tv + t) * HDv;
    float q1 = g_q[base + i], q2 = g_q[base + i + 64];
    g_qh[base + i]      = __float2half((q1 * c - q2 * s) * scale);
    g_qh[base + i + 64] = __float2half((q2 * c + q1 * s) * scale);
    float k1 = g_k[base + i], k2 = g_k[base + i + 64];
    g_kh[base + i]      = __float2half(k1 * c - k2 * s);
    g_kh[base + i + 64] = __float2half(k2 * c + k1 * s);
}

// ================= fp16 flash attention (R11-proven): Q in regs, 2-stage KV ========
#define ATT_SMEM_BYTES (16384 + 2 * 32768)

__global__ __launch_bounds__(128, 2) void attn_kernel()
{
    extern __shared__ __align__(1024) char smraw[];
    uint32_t sbase = smem_u32(smraw);

    int bh = blockIdx.y;
    int qb = gridDim.x - 1 - blockIdx.x;   // long CTAs first
    int q0 = qb * 64;
    int tid = threadIdx.x;
    int lane = tid & 31;
    int w = tid >> 5;
    int g = lane >> 2;
    int tg = lane & 3;
    int lrow = lane & 7;
    int sel = lane >> 3;
    size_t base = (size_t)bh * Tv * HDv;

#define ISSUE_KV(kt) do {                                                        \
        uint32_t kb_ = sbase + 16384 + ((kt) & 1) * 32768;                       \
        int k0_ = (kt) * 64;                                                     \
        for (int i = tid; i < 1024; i += 128) {                                  \
            int r_ = i >> 4, c_ = i & 15;                                        \
            cp16(kb_ + sw256(r_, c_),         &g_kh[base + (size_t)(k0_ + r_) * HDv + c_ * 8]); \
            cp16(kb_ + 16384 + sw256(r_, c_), &g_vh[base + (size_t)(k0_ + r_) * HDv + c_ * 8]); \
        }                                                                        \
        CP_COMMIT();                                                             \
    } while (0)

    for (int i = tid; i < 1024; i += 128) {
        int r = i >> 4, c = i & 15;
        cp16(sbase + sw256(r, c), &g_qh[base + (size_t)(q0 + r) * HDv + c * 8]);
    }
    {
        uint32_t kb = sbase + 16384;
        for (int i = tid; i < 1024; i += 128) {
            int r = i >> 4, c = i & 15;
            cp16(kb + sw256(r, c),         &g_kh[base + (size_t)r * HDv + c * 8]);
            cp16(kb + 16384 + sw256(r, c), &g_vh[base + (size_t)r * HDv + c * 8]);
        }
        CP_COMMIT();
    }
    if (qb >= 1) { ISSUE_KV(1); CP_WAIT1(); } else { CP_WAIT0(); }
    __syncthreads();

    uint4 aq[8];
#pragma unroll
    for (int ks = 0; ks < 8; ks++) {
        int row = w * 16 + ((sel & 1) << 3) + lrow;
        int ch  = ks * 2 + (sel >> 1);
        ldm4(aq[ks], sbase + sw256(row, ch));
    }

    float o[16][4];
#pragma unroll
    for (int nt = 0; nt < 16; nt++)
#pragma unroll
        for (int e = 0; e < 4; e++) o[nt][e] = 0.0f;
    float mrow0 = -1e30f, mrow1 = -1e30f;
    float lrow0 = 0.0f,   lrow1 = 0.0f;

    for (int kt = 0; kt <= qb; kt++) {
        if (kt < qb) CP_WAIT1(); else CP_WAIT0();
        __syncthreads();

        uint32_t kb = sbase + 16384 + (kt & 1) * 32768;
        uint32_t vb = kb + 16384;
        int k0 = kt * 64;

        float s[8][4];
#pragma unroll
        for (int nt = 0; nt < 8; nt++)
#pragma unroll
            for (int e = 0; e < 4; e++) s[nt][e] = 0.0f;
#pragma unroll
        for (int ks = 0; ks < 8; ks++) {
#pragma unroll
            for (int nt = 0; nt < 4; nt++) {
                int row = nt * 16 + ((sel >> 1) << 3) + lrow;
                int ch  = ks * 2 + (sel & 1);
                uint4 bk;
                ldm4(bk, kb + sw256(row, ch));
                mma_h(s[2 * nt],     aq[ks].x, aq[ks].y, aq[ks].z, aq[ks].w, bk.x, bk.y);
                mma_h(s[2 * nt + 1], aq[ks].x, aq[ks].y, aq[ks].z, aq[ks].w, bk.z, bk.w);
            }
        }

        if (kt == qb) {
            int row0 = q0 + w * 16 + g;
#pragma unroll
            for (int nt = 0; nt < 8; nt++)
#pragma unroll
                for (int e2 = 0; e2 < 4; e2++) {
                    int col = k0 + nt * 8 + tg * 2 + (e2 & 1);
                    int rr = row0 + (e2 >> 1) * 8;
                    if (col > rr) s[nt][e2] = -1e30f;
                }
        }

        float mx0 = -1e30f, mx1 = -1e30f;
#pragma unroll
        for (int nt = 0; nt < 8; nt++) {
            mx0 = fmaxf(mx0, fmaxf(s[nt][0], s[nt][1]));
            mx1 = fmaxf(mx1, fmaxf(s[nt][2], s[nt][3]));
        }
        mx0 = fmaxf(mx0, __shfl_xor_sync(0xffffffffu, mx0, 1));
        mx0 = fmaxf(mx0, __shfl_xor_sync(0xffffffffu, mx0, 2));
        mx1 = fmaxf(mx1, __shfl_xor_sync(0xffffffffu, mx1, 1));
        mx1 = fmaxf(mx1, __shfl_xor_sync(0xffffffffu, mx1, 2));

        float mn0 = fmaxf(mrow0, mx0);
        float mn1 = fmaxf(mrow1, mx1);
        float al0 = __expf(mrow0 - mn0);
        float al1 = __expf(mrow1 - mn1);
        mrow0 = mn0; mrow1 = mn1;

        float rs0 = 0.0f, rs1 = 0.0f;
#pragma unroll
        for (int nt = 0; nt < 8; nt++) {
            float p0 = __expf(s[nt][0] - mn0);
            float p1 = __expf(s[nt][1] - mn0);
            float p2 = __expf(s[nt][2] - mn1);
            float p3 = __expf(s[nt][3] - mn1);
            rs0 += p0 + p1; rs1 += p2 + p3;
            s[nt][0] = p0; s[nt][1] = p1; s[nt][2] = p2; s[nt][3] = p3;
        }
        rs0 += __shfl_xor_sync(0xffffffffu, rs0, 1);
        rs0 += __shfl_xor_sync(0xffffffffu, rs0, 2);
        rs1 += __shfl_xor_sync(0xffffffffu, rs1, 1);
        rs1 += __shfl_xor_sync(0xffffffffu, rs1, 2);
        lrow0 = lrow0 * al0 + rs0;
        lrow1 = lrow1 * al1 + rs1;

#pragma unroll
        for (int nt = 0; nt < 16; nt++) {
            o[nt][0] *= al0; o[nt][1] *= al0;
            o[nt][2] *= al1; o[nt][3] *= al1;
        }

#pragma unroll
        for (int ks2 = 0; ks2 < 4; ks2++) {
            unsigned a0 = h2pack(s[2 * ks2][0],     s[2 * ks2][1]);
            unsigned a1 = h2pack(s[2 * ks2][2],     s[2 * ks2][3]);
            unsigned a2 = h2pack(s[2 * ks2 + 1][0], s[2 * ks2 + 1][1]);
            unsigned a3 = h2pack(s[2 * ks2 + 1][2], s[2 * ks2 + 1][3]);
#pragma unroll
            for (int nt = 0; nt < 8; nt++) {
                int row = ks2 * 16 + ((sel & 1) << 3) + lrow;
                int ch  = nt * 2 + (sel >> 1);
                uint4 bv;
                ldm4t(bv, vb + sw256(row, ch));
                mma_h(o[2 * nt],     a0, a1, a2, a3, bv.x, bv.y);
                mma_h(o[2 * nt + 1], a0, a1, a2, a3, bv.z, bv.w);
            }
        }

        if (kt + 2 <= qb) {
            __syncthreads();
            ISSUE_KV(kt + 2);
        }
    }
#undef ISSUE_KV

    int b = bh >> 4;
    int hh = bh & 15;
#pragma unroll
    for (int h = 0; h < 2; h++) {
        float invl = 1.0f / (h ? lrow1 : lrow0);
        int t = q0 + w * 16 + g + h * 8;
        __half* op = g_yh + ((size_t)(b * Tv + t)) * Cv + hh * HDv;
#pragma unroll
        for (int nt = 0; nt < 16; nt++) {
            int d = nt * 8 + tg * 2;
            *(unsigned*)&op[d] = h2pack(o[nt][2 * h] * invl, o[nt][2 * h + 1] * invl);
        }
    }
}

// ---------------- launch ----------------
extern "C" void kernel_launch(void* const* d_in, const int* in_sizes, int n_in,
                              void* d_out, int out_size)
{
    const float* x  = (const float*)d_in[0];
    const float* wq = (const float*)d_in[2];
    const float* wk = (const float*)d_in[3];
    const float* wv = (const float*)d_in[4];
    const float* wo = (const float*)d_in[5];
    float* out = (float*)d_out;

    __half* whp = nullptr;
    __half* xhp = nullptr;
    __half* yhp = nullptr;
    cudaGetSymbolAddress((void**)&whp, g_wh);
    cudaGetSymbolAddress((void**)&xhp, g_xh);
    cudaGetSymbolAddress((void**)&yhp, g_yh);
    cudaFuncSetAttribute(h16gemm, cudaFuncAttributeMaxDynamicSharedMemorySize,
                         GEMM_SMEM_BYTES);
    cudaFuncSetAttribute(attn_kernel, cudaFuncAttributeMaxDynamicSharedMemorySize,
                         ATT_SMEM_BYTES);

    // fused conversions
    cvt_all<<<(unsigned)((NXe + 4 * NWe) / 1024), 256>>>(x, wq, wk, wv, wo);

    // merged QKV projection: N = 6144
    h16gemm<<<dim3(48, 64), 256, GEMM_SMEM_BYTES>>>(xhp, whp, nullptr, 4);

    rope_kernel<<<(BHv * Tv * 64) / 256, 256>>>();

    attn_kernel<<<dim3(Tv / 64, BHv), 128, ATT_SMEM_BYTES>>>();

    // output projection: N = 2048
    h16gemm<<<dim3(16, 64), 256, GEMM_SMEM_BYTES>>>(yhp, whp + 3 * NWe, out, 3);
}